// round 13
// baseline (speedup 1.0000x reference)
#include <cuda_runtime.h>
#include <math.h>

#define LN_EPS 1e-5f
#define ATT_SCALE 0.17677669529663687f

// ---------- scratch (device globals, no allocation) ----------
__device__ float g_xn  [(size_t)8192 * 256];
__device__ float g_q   [(size_t)8192 * 256];
__device__ float g_qWH [(size_t)8 * 8192 * 256];   // [h][row][c]
__device__ float g_ybarH[(size_t)8 * 8192 * 256];  // [h][row][c]
__device__ float g_a   [(size_t)8192 * 256];
__device__ float g_t   [(size_t)8192 * 256];
__device__ float g_h1  [(size_t)8192 * 512];
__device__ float g_zero[256];

#define FMA2(acc, a, b) asm("fma.rn.f32x2 %0, %1, %2, %0;" : "+l"(acc) : "l"(a), "l"(b))

__device__ __forceinline__ unsigned long long dup2(float a) {
    unsigned long long r; asm("mov.b64 %0, {%1, %1};" : "=l"(r) : "f"(a)); return r;
}
__device__ __forceinline__ float2 u2f(unsigned long long u) {
    float2 f; f.x = __uint_as_float((unsigned)u); f.y = __uint_as_float((unsigned)(u >> 32)); return f;
}
__device__ __forceinline__ float warp_sum(float v) {
#pragma unroll
    for (int o = 16; o; o >>= 1) v += __shfl_xor_sync(0xffffffffu, v, o);
    return v;
}

// =============================================================================
// kLNx: g_xn = LN(x)*w + b. Warp per row.
// =============================================================================
__global__ __launch_bounds__(256) void kLNx(
    const float* __restrict__ x, const float* __restrict__ w, const float* __restrict__ b)
{
    const int lane = threadIdx.x & 31, wrp = threadIdx.x >> 5;
    const int row = blockIdx.x * 8 + wrp;
    const float* xr = x + (size_t)row * 256;
    float4 v0 = *(const float4*)&xr[lane * 4];
    float4 v1 = *(const float4*)&xr[128 + lane * 4];
    float s = v0.x + v0.y + v0.z + v0.w + v1.x + v1.y + v1.z + v1.w;
    s = warp_sum(s);
    float mu = s * (1.f / 256.f), d, sq = 0.f;
    d = v0.x - mu; sq += d * d; d = v0.y - mu; sq += d * d;
    d = v0.z - mu; sq += d * d; d = v0.w - mu; sq += d * d;
    d = v1.x - mu; sq += d * d; d = v1.y - mu; sq += d * d;
    d = v1.z - mu; sq += d * d; d = v1.w - mu; sq += d * d;
    sq = warp_sum(sq);
    float rs = rsqrtf(sq * (1.f / 256.f) + LN_EPS);
    float4 w0 = *(const float4*)&w[lane * 4], w1 = *(const float4*)&w[128 + lane * 4];
    float4 b0 = *(const float4*)&b[lane * 4], b1 = *(const float4*)&b[128 + lane * 4];
    float4 o0, o1;
    o0.x = (v0.x - mu) * rs * w0.x + b0.x; o0.y = (v0.y - mu) * rs * w0.y + b0.y;
    o0.z = (v0.z - mu) * rs * w0.z + b0.z; o0.w = (v0.w - mu) * rs * w0.w + b0.w;
    o1.x = (v1.x - mu) * rs * w1.x + b1.x; o1.y = (v1.y - mu) * rs * w1.y + b1.y;
    o1.z = (v1.z - mu) * rs * w1.z + b1.z; o1.w = (v1.w - mu) * rs * w1.w + b1.w;
    float* orow = g_xn + (size_t)row * 256;
    *(float4*)&orow[lane * 4] = o0; *(float4*)&orow[128 + lane * 4] = o1;
}

// =============================================================================
// gemm256 (round-9 proven; qWH only): 64x256 tile, 8x8, double-buffered.
// =============================================================================
template<int EPI, bool WTRANS>
__global__ __launch_bounds__(256, 2) void gemm256(
    const float* __restrict__ A, int lda, int strideA,
    const float* __restrict__ W, int ldw, int strideW, int kin,
    const float* __restrict__ bias, int strideB,
    float* __restrict__ C, int ldc, int strideC)
{
    __shared__ __align__(16) float As[2][16][68];
    __shared__ __align__(16) float Ws[2][16][260];
    const int tid = threadIdx.x, lane = tid & 31, wrp = tid >> 5;
    const int row0 = blockIdx.x * 64;
    A += (size_t)blockIdx.y * strideA;
    W += (size_t)blockIdx.y * strideW;
    C += (size_t)blockIdx.y * strideC;
    bias += (size_t)blockIdx.y * strideB;

    unsigned long long acc[8][4];
#pragma unroll
    for (int r = 0; r < 8; r++) { acc[r][0] = 0; acc[r][1] = 0; acc[r][2] = 0; acc[r][3] = 0; }

    const int am = tid >> 2, akq = (tid & 3) * 4;
    const int kr = tid >> 4, nq = (tid & 15) * 16;
    float4 av, wv[4];

    av = *(const float4*)&A[(size_t)(row0 + am) * lda + akq];
    if (WTRANS) {
#pragma unroll
        for (int oo = 0; oo < 4; oo++)
            wv[oo] = *(const float4*)&W[(size_t)(oo * 64 + am) * ldw + akq];
    } else {
#pragma unroll
        for (int q = 0; q < 4; q++)
            wv[q] = *(const float4*)&W[(size_t)kr * ldw + nq + q * 4];
    }
    { float ae[4]; *(float4*)ae = av;
#pragma unroll
      for (int j = 0; j < 4; j++) As[0][akq + j][am] = ae[j]; }
    if (WTRANS) {
#pragma unroll
        for (int oo = 0; oo < 4; oo++) { float we[4]; *(float4*)we = wv[oo];
#pragma unroll
            for (int j = 0; j < 4; j++) Ws[0][akq + j][oo * 64 + am] = we[j]; }
    } else {
#pragma unroll
        for (int q = 0; q < 4; q++) *(float4*)&Ws[0][kr][nq + q * 4] = wv[q];
    }
    __syncthreads();

    int s = 0;
    for (int kc = 0; kc < kin; kc += 16) {
        const bool more = (kc + 16) < kin;
        if (more) {
            av = *(const float4*)&A[(size_t)(row0 + am) * lda + kc + 16 + akq];
            if (WTRANS) {
#pragma unroll
                for (int oo = 0; oo < 4; oo++)
                    wv[oo] = *(const float4*)&W[(size_t)(oo * 64 + am) * ldw + kc + 16 + akq];
            } else {
#pragma unroll
                for (int q = 0; q < 4; q++)
                    wv[q] = *(const float4*)&W[(size_t)(kc + 16 + kr) * ldw + nq + q * 4];
            }
        }

#pragma unroll
        for (int k = 0; k < 16; k++) {
            ulonglong2 w0 = *(const ulonglong2*)&Ws[s][k][lane * 4];
            ulonglong2 w1 = *(const ulonglong2*)&Ws[s][k][128 + lane * 4];
            float4 aA = *(const float4*)&As[s][k][wrp * 8];
            float4 aB = *(const float4*)&As[s][k][wrp * 8 + 4];
            float ar[8] = {aA.x, aA.y, aA.z, aA.w, aB.x, aB.y, aB.z, aB.w};
#pragma unroll
            for (int r = 0; r < 8; r++) {
                unsigned long long a2 = dup2(ar[r]);
                FMA2(acc[r][0], a2, w0.x); FMA2(acc[r][1], a2, w0.y);
                FMA2(acc[r][2], a2, w1.x); FMA2(acc[r][3], a2, w1.y);
            }
        }

        if (more) {
            const int ns = s ^ 1;
            { float ae[4]; *(float4*)ae = av;
#pragma unroll
              for (int j = 0; j < 4; j++) As[ns][akq + j][am] = ae[j]; }
            if (WTRANS) {
#pragma unroll
                for (int oo = 0; oo < 4; oo++) { float we[4]; *(float4*)we = wv[oo];
#pragma unroll
                    for (int j = 0; j < 4; j++) Ws[ns][akq + j][oo * 64 + am] = we[j]; }
            } else {
#pragma unroll
                for (int q = 0; q < 4; q++) *(float4*)&Ws[ns][kr][nq + q * 4] = wv[q];
            }
            __syncthreads();
        }
        s ^= 1;
    }

    const int cA = lane * 4, cB = 128 + lane * 4;
    float4 bA = *(const float4*)&bias[cA];
    float4 bB = *(const float4*)&bias[cB];
#pragma unroll
    for (int r = 0; r < 8; r++) {
        const int row = row0 + wrp * 8 + r;
        float2 p0 = u2f(acc[r][0]), p1 = u2f(acc[r][1]);
        float2 p2 = u2f(acc[r][2]), p3 = u2f(acc[r][3]);
        float4 o0 = {p0.x + bA.x, p0.y + bA.y, p1.x + bA.z, p1.y + bA.w};
        float4 o1 = {p2.x + bB.x, p2.y + bB.y, p3.x + bB.z, p3.y + bB.w};
        float* crow = C + (size_t)row * ldc;
        *(float4*)&crow[cA] = o0; *(float4*)&crow[cB] = o1;
    }
}

// =============================================================================
// gemm256h: 32-row x 256-col tile (grid 256 => full chip), thread tile 4x8,
// double-buffered, WTRANS weights, FUSED LN epilogues. EPI: 2 LN, 3 res+LN.
// (32-row structure correctness-proven in round 4; used for Wp/W2 only.)
// =============================================================================
template<int EPI>
__global__ __launch_bounds__(256) void gemm256h(
    const float* __restrict__ A, int lda,
    const float* __restrict__ W, int ldw, int kin,
    const float* __restrict__ bias,
    float* __restrict__ C, int ldc,
    const float* __restrict__ lnw, const float* __restrict__ lnb,
    const float* __restrict__ res, int ldres)
{
    __shared__ __align__(16) float As[2][16][36];
    __shared__ __align__(16) float Ws[2][16][260];
    const int tid = threadIdx.x, lane = tid & 31, wrp = tid >> 5;
    const int row0 = blockIdx.x * 32;

    unsigned long long acc[4][4];
#pragma unroll
    for (int r = 0; r < 4; r++) { acc[r][0]=0; acc[r][1]=0; acc[r][2]=0; acc[r][3]=0; }

    const int am = tid >> 2, akq = (tid & 3) * 4;   // W staging (all threads), A staging (tid<128)
    const bool aload = tid < 128;
    float4 av; float4 wv[4];

    if (aload) av = *(const float4*)&A[(size_t)(row0 + am) * lda + akq];
#pragma unroll
    for (int oo = 0; oo < 4; oo++)
        wv[oo] = *(const float4*)&W[(size_t)(oo * 64 + am) * ldw + akq];

    // stage chunk 0
    if (aload) { float ae[4]; *(float4*)ae = av;
#pragma unroll
        for (int j = 0; j < 4; j++) As[0][akq + j][am] = ae[j]; }
#pragma unroll
    for (int oo = 0; oo < 4; oo++) { float we[4]; *(float4*)we = wv[oo];
#pragma unroll
        for (int j = 0; j < 4; j++) Ws[0][akq + j][oo * 64 + am] = we[j]; }
    __syncthreads();

    int s = 0;
    for (int kc = 0; kc < kin; kc += 16) {
        const bool more = (kc + 16) < kin;
        if (more) {
            if (aload) av = *(const float4*)&A[(size_t)(row0 + am) * lda + kc + 16 + akq];
#pragma unroll
            for (int oo = 0; oo < 4; oo++)
                wv[oo] = *(const float4*)&W[(size_t)(oo * 64 + am) * ldw + kc + 16 + akq];
        }
#pragma unroll
        for (int k = 0; k < 16; k++) {
            ulonglong2 w0 = *(const ulonglong2*)&Ws[s][k][lane * 4];
            ulonglong2 w1 = *(const ulonglong2*)&Ws[s][k][128 + lane * 4];
            float4 aA = *(const float4*)&As[s][k][wrp * 4];
            float ar[4] = {aA.x, aA.y, aA.z, aA.w};
#pragma unroll
            for (int r = 0; r < 4; r++) {
                unsigned long long a2 = dup2(ar[r]);
                FMA2(acc[r][0], a2, w0.x); FMA2(acc[r][1], a2, w0.y);
                FMA2(acc[r][2], a2, w1.x); FMA2(acc[r][3], a2, w1.y);
            }
        }
        if (more) {
            int ns = s ^ 1;
            if (aload) { float ae[4]; *(float4*)ae = av;
#pragma unroll
                for (int j = 0; j < 4; j++) As[ns][akq + j][am] = ae[j]; }
#pragma unroll
            for (int oo = 0; oo < 4; oo++) { float we[4]; *(float4*)we = wv[oo];
#pragma unroll
                for (int j = 0; j < 4; j++) Ws[ns][akq + j][oo * 64 + am] = we[j]; }
            __syncthreads();
        }
        s ^= 1;
    }

    const int cA = lane * 4, cB = 128 + lane * 4;
    float4 bA = *(const float4*)&bias[cA];
    float4 bB = *(const float4*)&bias[cB];
    float4 lwA = *(const float4*)&lnw[cA], lwB = *(const float4*)&lnw[cB];
    float4 lbA = *(const float4*)&lnb[cA], lbB = *(const float4*)&lnb[cB];
#pragma unroll
    for (int r = 0; r < 4; r++) {
        const int row = row0 + wrp * 4 + r;
        float2 p0 = u2f(acc[r][0]), p1 = u2f(acc[r][1]);
        float2 p2 = u2f(acc[r][2]), p3 = u2f(acc[r][3]);
        float v[8];
        v[0] = p0.x + bA.x; v[1] = p0.y + bA.y; v[2] = p1.x + bA.z; v[3] = p1.y + bA.w;
        v[4] = p2.x + bB.x; v[5] = p2.y + bB.y; v[6] = p3.x + bB.z; v[7] = p3.y + bB.w;
        if (EPI == 3) {
            const float* rr = res + (size_t)row * ldres;
            float4 r0 = *(const float4*)&rr[cA], r1 = *(const float4*)&rr[cB];
            v[0] += r0.x; v[1] += r0.y; v[2] += r0.z; v[3] += r0.w;
            v[4] += r1.x; v[5] += r1.y; v[6] += r1.z; v[7] += r1.w;
        }
        float sm = v[0]+v[1]+v[2]+v[3]+v[4]+v[5]+v[6]+v[7];
        sm = warp_sum(sm);
        float mu = sm * (1.f / 256.f), sq = 0.f;
#pragma unroll
        for (int i = 0; i < 8; i++) { float d = v[i] - mu; sq += d * d; }
        sq = warp_sum(sq);
        float rs = rsqrtf(sq * (1.f / 256.f) + LN_EPS);
        v[0] = (v[0]-mu)*rs*lwA.x+lbA.x; v[1] = (v[1]-mu)*rs*lwA.y+lbA.y;
        v[2] = (v[2]-mu)*rs*lwA.z+lbA.z; v[3] = (v[3]-mu)*rs*lwA.w+lbA.w;
        v[4] = (v[4]-mu)*rs*lwB.x+lbB.x; v[5] = (v[5]-mu)*rs*lwB.y+lbB.y;
        v[6] = (v[6]-mu)*rs*lwB.z+lbB.z; v[7] = (v[7]-mu)*rs*lwB.w+lbB.w;
        float4 o0 = {v[0], v[1], v[2], v[3]}, o1 = {v[4], v[5], v[6], v[7]};
        float* crow = C + (size_t)row * ldc;
        *(float4*)&crow[cA] = o0; *(float4*)&crow[cB] = o1;
    }
}

// =============================================================================
// gemm128 (round-9 proven): 64x128 tile (N-split via blockIdx.z), thread tile
// 8x4, DOUBLE-BUFFERED. EPI: 0 bias, 1 gelu.
// =============================================================================
template<int EPI>
__global__ __launch_bounds__(256, 3) void gemm128(
    const float* __restrict__ A, int lda,
    const float* __restrict__ W, int ldw, int strideW, int kin,
    const float* __restrict__ bias, int strideB,
    float* __restrict__ C, int ldc, int strideC)
{
    __shared__ __align__(16) float As[2][16][68];
    __shared__ __align__(16) float Ws[2][16][132];
    const int tid = threadIdx.x, lane = tid & 31, wrp = tid >> 5;
    const int row0 = blockIdx.x * 64;
    const int colOff = blockIdx.z * 128;
    W += (size_t)blockIdx.y * strideW + (size_t)colOff * ldw;
    C += (size_t)blockIdx.y * strideC + colOff;
    bias += (size_t)blockIdx.y * strideB + colOff;

    unsigned long long acc[8][2];
#pragma unroll
    for (int r = 0; r < 8; r++) { acc[r][0] = 0; acc[r][1] = 0; }

    const int am = tid >> 2, akq = (tid & 3) * 4;
    float4 av, wv[2];

    av = *(const float4*)&A[(size_t)(row0 + am) * lda + akq];
#pragma unroll
    for (int oo = 0; oo < 2; oo++)
        wv[oo] = *(const float4*)&W[(size_t)(oo * 64 + am) * ldw + akq];
    { float ae[4]; *(float4*)ae = av;
#pragma unroll
      for (int j = 0; j < 4; j++) As[0][akq + j][am] = ae[j]; }
#pragma unroll
    for (int oo = 0; oo < 2; oo++) {
        float we[4]; *(float4*)we = wv[oo];
#pragma unroll
        for (int j = 0; j < 4; j++) Ws[0][akq + j][oo * 64 + am] = we[j];
    }
    __syncthreads();

    int s = 0;
    for (int kc = 0; kc < kin; kc += 16) {
        const bool more = (kc + 16) < kin;
        if (more) {
            av = *(const float4*)&A[(size_t)(row0 + am) * lda + kc + 16 + akq];
#pragma unroll
            for (int oo = 0; oo < 2; oo++)
                wv[oo] = *(const float4*)&W[(size_t)(oo * 64 + am) * ldw + kc + 16 + akq];
        }

#pragma unroll
        for (int k = 0; k < 16; k++) {
            ulonglong2 w0 = *(const ulonglong2*)&Ws[s][k][lane * 4];
            float4 aA = *(const float4*)&As[s][k][wrp * 8];
            float4 aB = *(const float4*)&As[s][k][wrp * 8 + 4];
            float ar[8] = {aA.x, aA.y, aA.z, aA.w, aB.x, aB.y, aB.z, aB.w};
#pragma unroll
            for (int r = 0; r < 8; r++) {
                unsigned long long a2 = dup2(ar[r]);
                FMA2(acc[r][0], a2, w0.x); FMA2(acc[r][1], a2, w0.y);
            }
        }

        if (more) {
            const int ns = s ^ 1;
            { float ae[4]; *(float4*)ae = av;
#pragma unroll
              for (int j = 0; j < 4; j++) As[ns][akq + j][am] = ae[j]; }
#pragma unroll
            for (int oo = 0; oo < 2; oo++) {
                float we[4]; *(float4*)we = wv[oo];
#pragma unroll
                for (int j = 0; j < 4; j++) Ws[ns][akq + j][oo * 64 + am] = we[j];
            }
            __syncthreads();
        }
        s ^= 1;
    }

    const int cA = lane * 4;
    float4 bA = *(const float4*)&bias[cA];
#pragma unroll
    for (int r = 0; r < 8; r++) {
        const int row = row0 + wrp * 8 + r;
        float2 p0 = u2f(acc[r][0]), p1 = u2f(acc[r][1]);
        float v[4] = {p0.x + bA.x, p0.y + bA.y, p1.x + bA.z, p1.y + bA.w};
        if (EPI == 1) {
#pragma unroll
            for (int i = 0; i < 4; i++)
                v[i] = 0.5f * v[i] * (1.0f + erff(v[i] * 0.70710678118654752f));
        }
        float4 o0 = {v[0], v[1], v[2], v[3]};
        *(float4*)&C[(size_t)row * ldc + cA] = o0;
    }
}

// =============================================================================
// kB (round-11 proven, 119us): register LN(y); logits 4 rows/thread c-quarter
// split; softmax combines 4 partials; ybar attnT 4-head fan-out.
// =============================================================================
__global__ __launch_bounds__(256) void kB(
    const float* __restrict__ y,
    const float* __restrict__ lnk_w,
    const float* __restrict__ lnv_w, const float* __restrict__ lnv_b)
{
    __shared__ __align__(16) float ysn[32][260];
    __shared__ __align__(16) float qWk[8][260];
    __shared__ float part[4][8][33];
    __shared__ __align__(16) float attnT[32][8];
    const int tid = threadIdx.x, lane = tid & 31, w = tid >> 5;
    const int bm = blockIdx.x;
    const float* ybase = y + (size_t)bm * 8192;

#pragma unroll
    for (int r = 0; r < 4; r++) {
        const int n = w * 4 + r;
        const float* yr = ybase + n * 256;
        float4 v0 = *(const float4*)&yr[lane * 4];
        float4 v1 = *(const float4*)&yr[128 + lane * 4];
        float s = v0.x+v0.y+v0.z+v0.w + v1.x+v1.y+v1.z+v1.w;
        s = warp_sum(s);
        float mu = s * (1.f / 256.f), d, sq = 0.f;
        d=v0.x-mu; sq+=d*d; d=v0.y-mu; sq+=d*d; d=v0.z-mu; sq+=d*d; d=v0.w-mu; sq+=d*d;
        d=v1.x-mu; sq+=d*d; d=v1.y-mu; sq+=d*d; d=v1.z-mu; sq+=d*d; d=v1.w-mu; sq+=d*d;
        sq = warp_sum(sq);
        float rs = rsqrtf(sq * (1.f / 256.f) + LN_EPS);
        float4 o0 = {(v0.x-mu)*rs, (v0.y-mu)*rs, (v0.z-mu)*rs, (v0.w-mu)*rs};
        float4 o1 = {(v1.x-mu)*rs, (v1.y-mu)*rs, (v1.z-mu)*rs, (v1.w-mu)*rs};
        *(float4*)&ysn[n][lane * 4] = o0;
        *(float4*)&ysn[n][128 + lane * 4] = o1;
    }
    {
        float lw = lnk_w[tid];
#pragma unroll
        for (int h = 0; h < 8; h++)
            qWk[h][tid] = g_qWH[((size_t)h * 8192 + bm) * 256 + tid] * lw;
    }
    __syncthreads();

    {
        const int cq = tid >> 6, h = tid & 7, nq = (tid >> 3) & 7;
        const int c0 = cq * 64;
        unsigned long long acc0 = 0, acc1 = 0, acc2 = 0, acc3 = 0;
#pragma unroll
        for (int c4 = 0; c4 < 16; c4++) {
            ulonglong2 qk = *(const ulonglong2*)&qWk[h][c0 + c4 * 4];
            ulonglong2 a0 = *(const ulonglong2*)&ysn[nq      ][c0 + c4 * 4];
            ulonglong2 a1 = *(const ulonglong2*)&ysn[nq +  8 ][c0 + c4 * 4];
            ulonglong2 a2 = *(const ulonglong2*)&ysn[nq + 16 ][c0 + c4 * 4];
            ulonglong2 a3 = *(const ulonglong2*)&ysn[nq + 24 ][c0 + c4 * 4];
            FMA2(acc0, a0.x, qk.x); FMA2(acc0, a0.y, qk.y);
            FMA2(acc1, a1.x, qk.x); FMA2(acc1, a1.y, qk.y);
            FMA2(acc2, a2.x, qk.x); FMA2(acc2, a2.y, qk.y);
            FMA2(acc3, a3.x, qk.x); FMA2(acc3, a3.y, qk.y);
        }
        float2 p0 = u2f(acc0), p1 = u2f(acc1), p2 = u2f(acc2), p3 = u2f(acc3);
        part[cq][h][nq]      = p0.x + p0.y;
        part[cq][h][nq + 8]  = p1.x + p1.y;
        part[cq][h][nq + 16] = p2.x + p2.y;
        part[cq][h][nq + 24] = p3.x + p3.y;
    }
    __syncthreads();

    {
        float v = (part[0][w][lane] + part[1][w][lane]
                 + part[2][w][lane] + part[3][w][lane]) * ATT_SCALE;
        float mx = v;
#pragma unroll
        for (int o = 16; o; o >>= 1) mx = fmaxf(mx, __shfl_xor_sync(0xffffffffu, mx, o));
        float e = __expf(v - mx);
        float s = warp_sum(e);
        attnT[lane][w] = e / s;
    }
    __syncthreads();

    {
        int cp = tid & 127, hbase = (tid >> 7) * 4;
        float lvw0 = lnv_w[cp * 2], lvw1 = lnv_w[cp * 2 + 1];
        float lvb0 = lnv_b[cp * 2], lvb1 = lnv_b[cp * 2 + 1];
        unsigned long long acc[4] = {0, 0, 0, 0};
#pragma unroll
        for (int n = 0; n < 32; n++) {
            unsigned long long y2 = *(const unsigned long long*)&ysn[n][cp * 2];
            float4 at = *(const float4*)&attnT[n][hbase];
            FMA2(acc[0], dup2(at.x), y2);
            FMA2(acc[1], dup2(at.y), y2);
            FMA2(acc[2], dup2(at.z), y2);
            FMA2(acc[3], dup2(at.w), y2);
        }
#pragma unroll
        for (int hh = 0; hh < 4; hh++) {
            float2 p = u2f(acc[hh]);
            float2 o = {p.x * lvw0 + lvb0, p.y * lvw1 + lvb1};
            *(float2*)&g_ybarH[((size_t)(hbase + hh) * 8192 + bm) * 256 + cp * 2] = o;
        }
    }
}

// =============================================================================
// aK (round-3 proven): per head a[:, h*32+d] = ybarH[h] @ Wv_h^T + bv.
// =============================================================================
__global__ __launch_bounds__(256, 2) void aK(
    const float* __restrict__ Wv, const float* __restrict__ bv)
{
    __shared__ __align__(16) float WsT[256][33];
    __shared__ __align__(16) float AsT[16][68];
    const int tid = threadIdx.x, lane = tid & 31, wrp = tid >> 5;
    const int row0 = blockIdx.x * 64;
    const int h = blockIdx.y;
    const float* A = g_ybarH + (size_t)h * 8192 * 256;

    {
        int d = tid >> 3, c8 = (tid & 7) * 4;
#pragma unroll
        for (int j = 0; j < 8; j++) {
            int c = c8 + j * 32;
            float4 v = *(const float4*)&Wv[(size_t)(h * 32 + d) * 256 + c];
            WsT[c][d] = v.x; WsT[c+1][d] = v.y; WsT[c+2][d] = v.z; WsT[c+3][d] = v.w;
        }
    }
    unsigned long long acc[4] = {0, 0, 0, 0};
    const int am = tid >> 2, akq = (tid & 3) * 4;
    float4 av = *(const float4*)&A[(size_t)(row0 + am) * 256 + akq];
    __syncthreads();

    for (int kc = 0; kc < 256; kc += 16) {
        { float ae[4]; *(float4*)ae = av;
#pragma unroll
          for (int j = 0; j < 4; j++) AsT[akq + j][am] = ae[j]; }
        __syncthreads();
        if (kc + 16 < 256)
            av = *(const float4*)&A[(size_t)(row0 + am) * 256 + kc + 16 + akq];
#pragma unroll
        for (int k = 0; k < 16; k++) {
            unsigned long long wd = dup2(WsT[kc + k][lane]);
            ulonglong2 a01 = *(const ulonglong2*)&AsT[k][wrp * 8];
            ulonglong2 a23 = *(const ulonglong2*)&AsT[k][wrp * 8 + 4];
            FMA2(acc[0], a01.x, wd); FMA2(acc[1], a01.y, wd);
            FMA2(acc[2], a23.x, wd); FMA2(acc[3], a23.y, wd);
        }
        __syncthreads();
    }
    float bvv = bv[h * 32 + lane];
#pragma unroll
    for (int i = 0; i < 4; i++) {
        float2 p = u2f(acc[i]);
        int row = row0 + wrp * 8 + 2 * i;
        g_a[(size_t)row * 256 + h * 32 + lane] = p.x + bvv;
        g_a[(size_t)(row + 1) * 256 + h * 32 + lane] = p.y + bvv;
    }
}

// =============================================================================
extern "C" void kernel_launch(void* const* d_in, const int* in_sizes, int n_in,
                              void* d_out, int out_size)
{
    const float* x      = (const float*)d_in[0];
    const float* y      = (const float*)d_in[1];
    const float* lnq_w  = (const float*)d_in[2];
    const float* lnq_b  = (const float*)d_in[3];
    const float* Wq     = (const float*)d_in[4];
    const float* bq     = (const float*)d_in[5];
    const float* lnk_w  = (const float*)d_in[6];
    const float* Wk     = (const float*)d_in[8];
    const float* lnv_w  = (const float*)d_in[10];
    const float* lnv_b  = (const float*)d_in[11];
    const float* Wv     = (const float*)d_in[12];
    const float* bv     = (const float*)d_in[13];
    const float* Wp     = (const float*)d_in[14];
    const float* bp     = (const float*)d_in[15];
    const float* pre_w  = (const float*)d_in[16];
    const float* pre_b  = (const float*)d_in[17];
    const float* W1     = (const float*)d_in[18];
    const float* b1     = (const float*)d_in[19];
    const float* W2     = (const float*)d_in[20];
    const float* b2     = (const float*)d_in[21];
    const float* post_w = (const float*)d_in[22];
    const float* post_b = (const float*)d_in[23];
    float* out = (float*)d_out;

    float* zg = nullptr; cudaGetSymbolAddress((void**)&zg, g_zero);
    float* xn = nullptr; cudaGetSymbolAddress((void**)&xn, g_xn);
    float* q  = nullptr; cudaGetSymbolAddress((void**)&q,  g_q);
    float* qWH= nullptr; cudaGetSymbolAddress((void**)&qWH,g_qWH);
    float* a  = nullptr; cudaGetSymbolAddress((void**)&a,  g_a);
    float* t  = nullptr; cudaGetSymbolAddress((void**)&t,  g_t);
    float* h1 = nullptr; cudaGetSymbolAddress((void**)&h1, g_h1);

    kLNx<<<1024, 256>>>(x, lnq_w, lnq_b);
    // q = LN(x) @ Wq^T + bq   (N-split, fills all SMs)
    gemm128<0><<<dim3(128, 1, 2), 256>>>(xn, 256, Wq, 256, 0, 256, bq, 0,
                                         q, 256, 0);
    // qWH[h] = q[:, h*32:+32] @ Wk[h*32:+32, :]
    gemm256<0, false><<<dim3(128, 8), 256>>>(q, 256, 32, Wk, 256, 32 * 256, 32, zg, 0,
                                             qWH, 256, 8192 * 256);
    kB<<<8192, 256>>>(y, lnk_w, lnv_w, lnv_b);
    aK<<<dim3(128, 8), 256>>>(Wv, bv);
    // t = LN(a @ Wp^T + bp)          (32-row tiles, grid 256: full chip, LN fused)
    gemm256h<2><<<256, 256>>>(a, 256, Wp, 256, 256, bp, t, 256,
                              pre_w, pre_b, nullptr, 0);
    // h1 = gelu(t @ W1^T + b1)   (N-split, fills all SMs)
    gemm128<1><<<dim3(128, 2, 2), 256>>>(t, 256, W1, 256, 256 * 256, 256, b1, 256,
                                         h1, 512, 256);
    // out = LN(t + h1 @ W2^T + b2)   (32-row tiles, grid 256: full chip, LN fused)
    gemm256h<3><<<256, 256>>>(h1, 512, W2, 512, 512, b2, out, 256,
                              post_w, post_b, t, 256);
}

// round 14
// speedup vs baseline: 1.0501x; 1.0501x over previous
#include <cuda_runtime.h>
#include <math.h>

#define LN_EPS 1e-5f
#define ATT_SCALE 0.17677669529663687f

// ---------- scratch (device globals, no allocation) ----------
__device__ float g_xn  [(size_t)8192 * 256];
__device__ float g_q   [(size_t)8192 * 256];
__device__ float g_qWH [(size_t)8 * 8192 * 256];   // [h][row][c]
__device__ float g_ybarH[(size_t)8 * 8192 * 256];  // [h][row][c]
__device__ float g_a   [(size_t)8192 * 256];
__device__ float g_t   [(size_t)8192 * 256];
__device__ float g_h1  [(size_t)8192 * 512];
__device__ float g_zero[256];

#define FMA2(acc, a, b) asm("fma.rn.f32x2 %0, %1, %2, %0;" : "+l"(acc) : "l"(a), "l"(b))

__device__ __forceinline__ unsigned long long dup2(float a) {
    unsigned long long r; asm("mov.b64 %0, {%1, %1};" : "=l"(r) : "f"(a)); return r;
}
__device__ __forceinline__ float2 u2f(unsigned long long u) {
    float2 f; f.x = __uint_as_float((unsigned)u); f.y = __uint_as_float((unsigned)(u >> 32)); return f;
}
__device__ __forceinline__ float warp_sum(float v) {
#pragma unroll
    for (int o = 16; o; o >>= 1) v += __shfl_xor_sync(0xffffffffu, v, o);
    return v;
}

// =============================================================================
// kLNx: g_xn = LN(x)*w + b. Warp per row.
// =============================================================================
__global__ __launch_bounds__(256) void kLNx(
    const float* __restrict__ x, const float* __restrict__ w, const float* __restrict__ b)
{
    const int lane = threadIdx.x & 31, wrp = threadIdx.x >> 5;
    const int row = blockIdx.x * 8 + wrp;
    const float* xr = x + (size_t)row * 256;
    float4 v0 = *(const float4*)&xr[lane * 4];
    float4 v1 = *(const float4*)&xr[128 + lane * 4];
    float s = v0.x + v0.y + v0.z + v0.w + v1.x + v1.y + v1.z + v1.w;
    s = warp_sum(s);
    float mu = s * (1.f / 256.f), d, sq = 0.f;
    d = v0.x - mu; sq += d * d; d = v0.y - mu; sq += d * d;
    d = v0.z - mu; sq += d * d; d = v0.w - mu; sq += d * d;
    d = v1.x - mu; sq += d * d; d = v1.y - mu; sq += d * d;
    d = v1.z - mu; sq += d * d; d = v1.w - mu; sq += d * d;
    sq = warp_sum(sq);
    float rs = rsqrtf(sq * (1.f / 256.f) + LN_EPS);
    float4 w0 = *(const float4*)&w[lane * 4], w1 = *(const float4*)&w[128 + lane * 4];
    float4 b0 = *(const float4*)&b[lane * 4], b1 = *(const float4*)&b[128 + lane * 4];
    float4 o0, o1;
    o0.x = (v0.x - mu) * rs * w0.x + b0.x; o0.y = (v0.y - mu) * rs * w0.y + b0.y;
    o0.z = (v0.z - mu) * rs * w0.z + b0.z; o0.w = (v0.w - mu) * rs * w0.w + b0.w;
    o1.x = (v1.x - mu) * rs * w1.x + b1.x; o1.y = (v1.y - mu) * rs * w1.y + b1.y;
    o1.z = (v1.z - mu) * rs * w1.z + b1.z; o1.w = (v1.w - mu) * rs * w1.w + b1.w;
    float* orow = g_xn + (size_t)row * 256;
    *(float4*)&orow[lane * 4] = o0; *(float4*)&orow[128 + lane * 4] = o1;
}

// =============================================================================
// gemm256 (round-9/11 proven): 64x256 tile, thread tile 8x8, DOUBLE-BUFFERED.
// EPI: 0 bias, 1 gelu, 2 LN, 3 res+LN.  WTRANS: W is [256n][K]; else [K][256n].
// =============================================================================
template<int EPI, bool WTRANS>
__global__ __launch_bounds__(256, 2) void gemm256(
    const float* __restrict__ A, int lda, int strideA,
    const float* __restrict__ W, int ldw, int strideW, int kin,
    const float* __restrict__ bias, int strideB,
    float* __restrict__ C, int ldc, int strideC,
    const float* __restrict__ lnw, const float* __restrict__ lnb,
    const float* __restrict__ res, int ldres)
{
    __shared__ __align__(16) float As[2][16][68];
    __shared__ __align__(16) float Ws[2][16][260];
    const int tid = threadIdx.x, lane = tid & 31, wrp = tid >> 5;
    const int row0 = blockIdx.x * 64;
    A += (size_t)blockIdx.y * strideA;
    W += (size_t)blockIdx.y * strideW;
    C += (size_t)blockIdx.y * strideC;
    bias += (size_t)blockIdx.y * strideB;

    unsigned long long acc[8][4];
#pragma unroll
    for (int r = 0; r < 8; r++) { acc[r][0] = 0; acc[r][1] = 0; acc[r][2] = 0; acc[r][3] = 0; }

    const int am = tid >> 2, akq = (tid & 3) * 4;
    const int kr = tid >> 4, nq = (tid & 15) * 16;
    float4 av, wv[4];

    av = *(const float4*)&A[(size_t)(row0 + am) * lda + akq];
    if (WTRANS) {
#pragma unroll
        for (int oo = 0; oo < 4; oo++)
            wv[oo] = *(const float4*)&W[(size_t)(oo * 64 + am) * ldw + akq];
    } else {
#pragma unroll
        for (int q = 0; q < 4; q++)
            wv[q] = *(const float4*)&W[(size_t)kr * ldw + nq + q * 4];
    }
    // stage chunk 0 -> buffer 0
    { float ae[4]; *(float4*)ae = av;
#pragma unroll
      for (int j = 0; j < 4; j++) As[0][akq + j][am] = ae[j]; }
    if (WTRANS) {
#pragma unroll
        for (int oo = 0; oo < 4; oo++) { float we[4]; *(float4*)we = wv[oo];
#pragma unroll
            for (int j = 0; j < 4; j++) Ws[0][akq + j][oo * 64 + am] = we[j]; }
    } else {
#pragma unroll
        for (int q = 0; q < 4; q++) *(float4*)&Ws[0][kr][nq + q * 4] = wv[q];
    }
    __syncthreads();

    int s = 0;
    for (int kc = 0; kc < kin; kc += 16) {
        const bool more = (kc + 16) < kin;
        if (more) {
            av = *(const float4*)&A[(size_t)(row0 + am) * lda + kc + 16 + akq];
            if (WTRANS) {
#pragma unroll
                for (int oo = 0; oo < 4; oo++)
                    wv[oo] = *(const float4*)&W[(size_t)(oo * 64 + am) * ldw + kc + 16 + akq];
            } else {
#pragma unroll
                for (int q = 0; q < 4; q++)
                    wv[q] = *(const float4*)&W[(size_t)(kc + 16 + kr) * ldw + nq + q * 4];
            }
        }

#pragma unroll
        for (int k = 0; k < 16; k++) {
            ulonglong2 w0 = *(const ulonglong2*)&Ws[s][k][lane * 4];
            ulonglong2 w1 = *(const ulonglong2*)&Ws[s][k][128 + lane * 4];
            float4 aA = *(const float4*)&As[s][k][wrp * 8];
            float4 aB = *(const float4*)&As[s][k][wrp * 8 + 4];
            float ar[8] = {aA.x, aA.y, aA.z, aA.w, aB.x, aB.y, aB.z, aB.w};
#pragma unroll
            for (int r = 0; r < 8; r++) {
                unsigned long long a2 = dup2(ar[r]);
                FMA2(acc[r][0], a2, w0.x); FMA2(acc[r][1], a2, w0.y);
                FMA2(acc[r][2], a2, w1.x); FMA2(acc[r][3], a2, w1.y);
            }
        }

        if (more) {
            const int ns = s ^ 1;
            { float ae[4]; *(float4*)ae = av;
#pragma unroll
              for (int j = 0; j < 4; j++) As[ns][akq + j][am] = ae[j]; }
            if (WTRANS) {
#pragma unroll
                for (int oo = 0; oo < 4; oo++) { float we[4]; *(float4*)we = wv[oo];
#pragma unroll
                    for (int j = 0; j < 4; j++) Ws[ns][akq + j][oo * 64 + am] = we[j]; }
            } else {
#pragma unroll
                for (int q = 0; q < 4; q++) *(float4*)&Ws[ns][kr][nq + q * 4] = wv[q];
            }
            __syncthreads();
        }
        s ^= 1;
    }

    const int cA = lane * 4, cB = 128 + lane * 4;
    float4 bA = *(const float4*)&bias[cA];
    float4 bB = *(const float4*)&bias[cB];
    float4 lwA, lwB, lbA, lbB;
    if (EPI >= 2) {
        lwA = *(const float4*)&lnw[cA]; lwB = *(const float4*)&lnw[cB];
        lbA = *(const float4*)&lnb[cA]; lbB = *(const float4*)&lnb[cB];
    }
#pragma unroll
    for (int r = 0; r < 8; r++) {
        const int row = row0 + wrp * 8 + r;
        float2 p0 = u2f(acc[r][0]), p1 = u2f(acc[r][1]);
        float2 p2 = u2f(acc[r][2]), p3 = u2f(acc[r][3]);
        float v[8];
        v[0] = p0.x + bA.x; v[1] = p0.y + bA.y; v[2] = p1.x + bA.z; v[3] = p1.y + bA.w;
        v[4] = p2.x + bB.x; v[5] = p2.y + bB.y; v[6] = p3.x + bB.z; v[7] = p3.y + bB.w;
        if (EPI == 1) {
#pragma unroll
            for (int i = 0; i < 8; i++)
                v[i] = 0.5f * v[i] * (1.0f + erff(v[i] * 0.70710678118654752f));
        }
        if (EPI == 3) {
            const float* rr = res + (size_t)row * ldres;
            float4 r0 = *(const float4*)&rr[cA], r1 = *(const float4*)&rr[cB];
            v[0] += r0.x; v[1] += r0.y; v[2] += r0.z; v[3] += r0.w;
            v[4] += r1.x; v[5] += r1.y; v[6] += r1.z; v[7] += r1.w;
        }
        if (EPI >= 2) {
            float sm = v[0]+v[1]+v[2]+v[3]+v[4]+v[5]+v[6]+v[7];
            sm = warp_sum(sm);
            float mu = sm * (1.f / 256.f), sq = 0.f;
#pragma unroll
            for (int i = 0; i < 8; i++) { float d = v[i] - mu; sq += d * d; }
            sq = warp_sum(sq);
            float rs = rsqrtf(sq * (1.f / 256.f) + LN_EPS);
            v[0] = (v[0]-mu)*rs*lwA.x+lbA.x; v[1] = (v[1]-mu)*rs*lwA.y+lbA.y;
            v[2] = (v[2]-mu)*rs*lwA.z+lbA.z; v[3] = (v[3]-mu)*rs*lwA.w+lbA.w;
            v[4] = (v[4]-mu)*rs*lwB.x+lbB.x; v[5] = (v[5]-mu)*rs*lwB.y+lbB.y;
            v[6] = (v[6]-mu)*rs*lwB.z+lbB.z; v[7] = (v[7]-mu)*rs*lwB.w+lbB.w;
        }
        float4 o0 = {v[0], v[1], v[2], v[3]}, o1 = {v[4], v[5], v[6], v[7]};
        float* crow = C + (size_t)row * ldc;
        *(float4*)&crow[cA] = o0; *(float4*)&crow[cB] = o1;
    }
}

// =============================================================================
// gemm128 (round-9 proven): 64x128 tile (N-split via blockIdx.z), thread tile
// 8x4, DOUBLE-BUFFERED. EPI: 0 bias, 1 gelu.
// =============================================================================
template<int EPI>
__global__ __launch_bounds__(256, 3) void gemm128(
    const float* __restrict__ A, int lda,
    const float* __restrict__ W, int ldw, int strideW, int kin,
    const float* __restrict__ bias, int strideB,
    float* __restrict__ C, int ldc, int strideC)
{
    __shared__ __align__(16) float As[2][16][68];
    __shared__ __align__(16) float Ws[2][16][132];
    const int tid = threadIdx.x, lane = tid & 31, wrp = tid >> 5;
    const int row0 = blockIdx.x * 64;
    const int colOff = blockIdx.z * 128;
    W += (size_t)blockIdx.y * strideW + (size_t)colOff * ldw;
    C += (size_t)blockIdx.y * strideC + colOff;
    bias += (size_t)blockIdx.y * strideB + colOff;

    unsigned long long acc[8][2];
#pragma unroll
    for (int r = 0; r < 8; r++) { acc[r][0] = 0; acc[r][1] = 0; }

    const int am = tid >> 2, akq = (tid & 3) * 4;
    float4 av, wv[2];

    av = *(const float4*)&A[(size_t)(row0 + am) * lda + akq];
#pragma unroll
    for (int oo = 0; oo < 2; oo++)
        wv[oo] = *(const float4*)&W[(size_t)(oo * 64 + am) * ldw + akq];
    { float ae[4]; *(float4*)ae = av;
#pragma unroll
      for (int j = 0; j < 4; j++) As[0][akq + j][am] = ae[j]; }
#pragma unroll
    for (int oo = 0; oo < 2; oo++) {
        float we[4]; *(float4*)we = wv[oo];
#pragma unroll
        for (int j = 0; j < 4; j++) Ws[0][akq + j][oo * 64 + am] = we[j];
    }
    __syncthreads();

    int s = 0;
    for (int kc = 0; kc < kin; kc += 16) {
        const bool more = (kc + 16) < kin;
        if (more) {
            av = *(const float4*)&A[(size_t)(row0 + am) * lda + kc + 16 + akq];
#pragma unroll
            for (int oo = 0; oo < 2; oo++)
                wv[oo] = *(const float4*)&W[(size_t)(oo * 64 + am) * ldw + kc + 16 + akq];
        }

#pragma unroll
        for (int k = 0; k < 16; k++) {
            ulonglong2 w0 = *(const ulonglong2*)&Ws[s][k][lane * 4];
            float4 aA = *(const float4*)&As[s][k][wrp * 8];
            float4 aB = *(const float4*)&As[s][k][wrp * 8 + 4];
            float ar[8] = {aA.x, aA.y, aA.z, aA.w, aB.x, aB.y, aB.z, aB.w};
#pragma unroll
            for (int r = 0; r < 8; r++) {
                unsigned long long a2 = dup2(ar[r]);
                FMA2(acc[r][0], a2, w0.x); FMA2(acc[r][1], a2, w0.y);
            }
        }

        if (more) {
            const int ns = s ^ 1;
            { float ae[4]; *(float4*)ae = av;
#pragma unroll
              for (int j = 0; j < 4; j++) As[ns][akq + j][am] = ae[j]; }
#pragma unroll
            for (int oo = 0; oo < 2; oo++) {
                float we[4]; *(float4*)we = wv[oo];
#pragma unroll
                for (int j = 0; j < 4; j++) Ws[ns][akq + j][oo * 64 + am] = we[j];
            }
            __syncthreads();
        }
        s ^= 1;
    }

    const int cA = lane * 4;
    float4 bA = *(const float4*)&bias[cA];
#pragma unroll
    for (int r = 0; r < 8; r++) {
        const int row = row0 + wrp * 8 + r;
        float2 p0 = u2f(acc[r][0]), p1 = u2f(acc[r][1]);
        float v[4] = {p0.x + bA.x, p0.y + bA.y, p1.x + bA.z, p1.y + bA.w};
        if (EPI == 1) {
#pragma unroll
            for (int i = 0; i < 4; i++)
                v[i] = 0.5f * v[i] * (1.0f + erff(v[i] * 0.70710678118654752f));
        }
        float4 o0 = {v[0], v[1], v[2], v[3]};
        *(float4*)&C[(size_t)row * ldc + cA] = o0;
    }
}

// =============================================================================
// kB (round-11 proven, 119us): register LN(y); logits 4 rows/thread c-quarter
// split; softmax combines 4 partials; ybar attnT 4-head fan-out.
// =============================================================================
__global__ __launch_bounds__(256) void kB(
    const float* __restrict__ y,
    const float* __restrict__ lnk_w,
    const float* __restrict__ lnv_w, const float* __restrict__ lnv_b)
{
    __shared__ __align__(16) float ysn[32][260];
    __shared__ __align__(16) float qWk[8][260];
    __shared__ float part[4][8][33];
    __shared__ __align__(16) float attnT[32][8];
    const int tid = threadIdx.x, lane = tid & 31, w = tid >> 5;
    const int bm = blockIdx.x;
    const float* ybase = y + (size_t)bm * 8192;

#pragma unroll
    for (int r = 0; r < 4; r++) {
        const int n = w * 4 + r;
        const float* yr = ybase + n * 256;
        float4 v0 = *(const float4*)&yr[lane * 4];
        float4 v1 = *(const float4*)&yr[128 + lane * 4];
        float s = v0.x+v0.y+v0.z+v0.w + v1.x+v1.y+v1.z+v1.w;
        s = warp_sum(s);
        float mu = s * (1.f / 256.f), d, sq = 0.f;
        d=v0.x-mu; sq+=d*d; d=v0.y-mu; sq+=d*d; d=v0.z-mu; sq+=d*d; d=v0.w-mu; sq+=d*d;
        d=v1.x-mu; sq+=d*d; d=v1.y-mu; sq+=d*d; d=v1.z-mu; sq+=d*d; d=v1.w-mu; sq+=d*d;
        sq = warp_sum(sq);
        float rs = rsqrtf(sq * (1.f / 256.f) + LN_EPS);
        float4 o0 = {(v0.x-mu)*rs, (v0.y-mu)*rs, (v0.z-mu)*rs, (v0.w-mu)*rs};
        float4 o1 = {(v1.x-mu)*rs, (v1.y-mu)*rs, (v1.z-mu)*rs, (v1.w-mu)*rs};
        *(float4*)&ysn[n][lane * 4] = o0;
        *(float4*)&ysn[n][128 + lane * 4] = o1;
    }
    {
        float lw = lnk_w[tid];
#pragma unroll
        for (int h = 0; h < 8; h++)
            qWk[h][tid] = g_qWH[((size_t)h * 8192 + bm) * 256 + tid] * lw;
    }
    __syncthreads();

    {
        const int cq = tid >> 6, h = tid & 7, nq = (tid >> 3) & 7;
        const int c0 = cq * 64;
        unsigned long long acc0 = 0, acc1 = 0, acc2 = 0, acc3 = 0;
#pragma unroll
        for (int c4 = 0; c4 < 16; c4++) {
            ulonglong2 qk = *(const ulonglong2*)&qWk[h][c0 + c4 * 4];
            ulonglong2 a0 = *(const ulonglong2*)&ysn[nq      ][c0 + c4 * 4];
            ulonglong2 a1 = *(const ulonglong2*)&ysn[nq +  8 ][c0 + c4 * 4];
            ulonglong2 a2 = *(const ulonglong2*)&ysn[nq + 16 ][c0 + c4 * 4];
            ulonglong2 a3 = *(const ulonglong2*)&ysn[nq + 24 ][c0 + c4 * 4];
            FMA2(acc0, a0.x, qk.x); FMA2(acc0, a0.y, qk.y);
            FMA2(acc1, a1.x, qk.x); FMA2(acc1, a1.y, qk.y);
            FMA2(acc2, a2.x, qk.x); FMA2(acc2, a2.y, qk.y);
            FMA2(acc3, a3.x, qk.x); FMA2(acc3, a3.y, qk.y);
        }
        float2 p0 = u2f(acc0), p1 = u2f(acc1), p2 = u2f(acc2), p3 = u2f(acc3);
        part[cq][h][nq]      = p0.x + p0.y;
        part[cq][h][nq + 8]  = p1.x + p1.y;
        part[cq][h][nq + 16] = p2.x + p2.y;
        part[cq][h][nq + 24] = p3.x + p3.y;
    }
    __syncthreads();

    {
        float v = (part[0][w][lane] + part[1][w][lane]
                 + part[2][w][lane] + part[3][w][lane]) * ATT_SCALE;
        float mx = v;
#pragma unroll
        for (int o = 16; o; o >>= 1) mx = fmaxf(mx, __shfl_xor_sync(0xffffffffu, mx, o));
        float e = __expf(v - mx);
        float s = warp_sum(e);
        attnT[lane][w] = e / s;
    }
    __syncthreads();

    {
        int cp = tid & 127, hbase = (tid >> 7) * 4;
        float lvw0 = lnv_w[cp * 2], lvw1 = lnv_w[cp * 2 + 1];
        float lvb0 = lnv_b[cp * 2], lvb1 = lnv_b[cp * 2 + 1];
        unsigned long long acc[4] = {0, 0, 0, 0};
#pragma unroll
        for (int n = 0; n < 32; n++) {
            unsigned long long y2 = *(const unsigned long long*)&ysn[n][cp * 2];
            float4 at = *(const float4*)&attnT[n][hbase];
            FMA2(acc[0], dup2(at.x), y2);
            FMA2(acc[1], dup2(at.y), y2);
            FMA2(acc[2], dup2(at.z), y2);
            FMA2(acc[3], dup2(at.w), y2);
        }
#pragma unroll
        for (int hh = 0; hh < 4; hh++) {
            float2 p = u2f(acc[hh]);
            float2 o = {p.x * lvw0 + lvb0, p.y * lvw1 + lvb1};
            *(float2*)&g_ybarH[((size_t)(hbase + hh) * 8192 + bm) * 256 + cp * 2] = o;
        }
    }
}

// =============================================================================
// aK: per head a[:, h*32+d] = ybarH[h] @ Wv_h^T + bv. NOW double-buffered AsT
// (one sync per chunk; staging overlaps compute — round-9-proven pattern).
// =============================================================================
__global__ __launch_bounds__(256, 2) void aK(
    const float* __restrict__ Wv, const float* __restrict__ bv)
{
    __shared__ __align__(16) float WsT[256][33];
    __shared__ __align__(16) float AsT[2][16][68];
    const int tid = threadIdx.x, lane = tid & 31, wrp = tid >> 5;
    const int row0 = blockIdx.x * 64;
    const int h = blockIdx.y;
    const float* A = g_ybarH + (size_t)h * 8192 * 256;

    {   // stage Wv_h transposed: WsT[c][d] (read-only thereafter)
        int d = tid >> 3, c8 = (tid & 7) * 4;
#pragma unroll
        for (int j = 0; j < 8; j++) {
            int c = c8 + j * 32;
            float4 v = *(const float4*)&Wv[(size_t)(h * 32 + d) * 256 + c];
            WsT[c][d] = v.x; WsT[c+1][d] = v.y; WsT[c+2][d] = v.z; WsT[c+3][d] = v.w;
        }
    }
    unsigned long long acc[4] = {0, 0, 0, 0};
    const int am = tid >> 2, akq = (tid & 3) * 4;
    float4 av = *(const float4*)&A[(size_t)(row0 + am) * 256 + akq];
    // stage chunk 0 -> buffer 0
    { float ae[4]; *(float4*)ae = av;
#pragma unroll
      for (int j = 0; j < 4; j++) AsT[0][akq + j][am] = ae[j]; }
    __syncthreads();

    int s = 0;
    for (int kc = 0; kc < 256; kc += 16) {
        const bool more = (kc + 16) < 256;
        if (more)
            av = *(const float4*)&A[(size_t)(row0 + am) * 256 + kc + 16 + akq];
#pragma unroll
        for (int k = 0; k < 16; k++) {
            unsigned long long wd = dup2(WsT[kc + k][lane]);
            ulonglong2 a01 = *(const ulonglong2*)&AsT[s][k][wrp * 8];
            ulonglong2 a23 = *(const ulonglong2*)&AsT[s][k][wrp * 8 + 4];
            FMA2(acc[0], a01.x, wd); FMA2(acc[1], a01.y, wd);
            FMA2(acc[2], a23.x, wd); FMA2(acc[3], a23.y, wd);
        }
        if (more) {
            const int ns = s ^ 1;
            float ae[4]; *(float4*)ae = av;
#pragma unroll
            for (int j = 0; j < 4; j++) AsT[ns][akq + j][am] = ae[j];
            __syncthreads();
        }
        s ^= 1;
    }
    float bvv = bv[h * 32 + lane];
#pragma unroll
    for (int i = 0; i < 4; i++) {
        float2 p = u2f(acc[i]);
        int row = row0 + wrp * 8 + 2 * i;
        g_a[(size_t)row * 256 + h * 32 + lane] = p.x + bvv;
        g_a[(size_t)(row + 1) * 256 + h * 32 + lane] = p.y + bvv;
    }
}

// =============================================================================
extern "C" void kernel_launch(void* const* d_in, const int* in_sizes, int n_in,
                              void* d_out, int out_size)
{
    const float* x      = (const float*)d_in[0];
    const float* y      = (const float*)d_in[1];
    const float* lnq_w  = (const float*)d_in[2];
    const float* lnq_b  = (const float*)d_in[3];
    const float* Wq     = (const float*)d_in[4];
    const float* bq     = (const float*)d_in[5];
    const float* lnk_w  = (const float*)d_in[6];
    const float* Wk     = (const float*)d_in[8];
    const float* lnv_w  = (const float*)d_in[10];
    const float* lnv_b  = (const float*)d_in[11];
    const float* Wv     = (const float*)d_in[12];
    const float* bv     = (const float*)d_in[13];
    const float* Wp     = (const float*)d_in[14];
    const float* bp     = (const float*)d_in[15];
    const float* pre_w  = (const float*)d_in[16];
    const float* pre_b  = (const float*)d_in[17];
    const float* W1     = (const float*)d_in[18];
    const float* b1     = (const float*)d_in[19];
    const float* W2     = (const float*)d_in[20];
    const float* b2     = (const float*)d_in[21];
    const float* post_w = (const float*)d_in[22];
    const float* post_b = (const float*)d_in[23];
    float* out = (float*)d_out;

    float* zg = nullptr; cudaGetSymbolAddress((void**)&zg, g_zero);
    float* xn = nullptr; cudaGetSymbolAddress((void**)&xn, g_xn);
    float* q  = nullptr; cudaGetSymbolAddress((void**)&q,  g_q);
    float* qWH= nullptr; cudaGetSymbolAddress((void**)&qWH,g_qWH);
    float* a  = nullptr; cudaGetSymbolAddress((void**)&a,  g_a);
    float* t  = nullptr; cudaGetSymbolAddress((void**)&t,  g_t);
    float* h1 = nullptr; cudaGetSymbolAddress((void**)&h1, g_h1);

    kLNx<<<1024, 256>>>(x, lnq_w, lnq_b);
    // q = LN(x) @ Wq^T + bq   (N-split, fills all SMs)
    gemm128<0><<<dim3(128, 1, 2), 256>>>(xn, 256, Wq, 256, 0, 256, bq, 0,
                                         q, 256, 0);
    // qWH[h] = q[:, h*32:+32] @ Wk[h*32:+32, :]
    gemm256<0, false><<<dim3(128, 8), 256>>>(q, 256, 32, Wk, 256, 32 * 256, 32, zg, 0,
                                             qWH, 256, 8192 * 256, nullptr, nullptr, nullptr, 0);
    kB<<<8192, 256>>>(y, lnk_w, lnv_w, lnv_b);
    aK<<<dim3(128, 8), 256>>>(Wv, bv);
    // t = LN(a @ Wp^T + bp)   (64-row fused-LN — best known form for Wp)
    gemm256<2, true ><<<dim3(128, 1), 256>>>(a, 256, 0, Wp, 256, 0, 256, bp, 0,
                                             t, 256, 0, pre_w, pre_b, nullptr, 0);
    // h1 = gelu(t @ W1^T + b1)   (N-split, fills all SMs)
    gemm128<1><<<dim3(128, 2, 2), 256>>>(t, 256, W1, 256, 256 * 256, 256, b1, 256,
                                         h1, 512, 256);
    // out = LN(t + h1 @ W2^T + b2)   (64-row fused-LN — best known form for W2)
    gemm256<3, true ><<<dim3(128, 1), 256>>>(h1, 512, 0, W2, 512, 0, 512, b2, 0,
                                             out, 256, 0, post_w, post_b, t, 256);
}

// round 15
// speedup vs baseline: 1.0562x; 1.0059x over previous
#include <cuda_runtime.h>
#include <math.h>

#define LN_EPS 1e-5f
#define ATT_SCALE 0.17677669529663687f

// ---------- scratch (device globals, no allocation) ----------
__device__ float g_xn  [(size_t)8192 * 256];
__device__ float g_q   [(size_t)8192 * 256];
__device__ float g_qWH [(size_t)8 * 8192 * 256];   // [h][row][c]
__device__ float g_ybarH[(size_t)8 * 8192 * 256];  // [h][row][c]
__device__ float g_a   [(size_t)8192 * 256];
__device__ float g_t   [(size_t)8192 * 256];
__device__ float g_h1  [(size_t)8192 * 512];
__device__ float g_zero[256];

#define FMA2(acc, a, b) asm("fma.rn.f32x2 %0, %1, %2, %0;" : "+l"(acc) : "l"(a), "l"(b))

__device__ __forceinline__ unsigned long long dup2(float a) {
    unsigned long long r; asm("mov.b64 %0, {%1, %1};" : "=l"(r) : "f"(a)); return r;
}
__device__ __forceinline__ float2 u2f(unsigned long long u) {
    float2 f; f.x = __uint_as_float((unsigned)u); f.y = __uint_as_float((unsigned)(u >> 32)); return f;
}
__device__ __forceinline__ float warp_sum(float v) {
#pragma unroll
    for (int o = 16; o; o >>= 1) v += __shfl_xor_sync(0xffffffffu, v, o);
    return v;
}

// =============================================================================
// kLNx: g_xn = LN(x)*w + b. Warp per row.
// =============================================================================
__global__ __launch_bounds__(256) void kLNx(
    const float* __restrict__ x, const float* __restrict__ w, const float* __restrict__ b)
{
    const int lane = threadIdx.x & 31, wrp = threadIdx.x >> 5;
    const int row = blockIdx.x * 8 + wrp;
    const float* xr = x + (size_t)row * 256;
    float4 v0 = *(const float4*)&xr[lane * 4];
    float4 v1 = *(const float4*)&xr[128 + lane * 4];
    float s = v0.x + v0.y + v0.z + v0.w + v1.x + v1.y + v1.z + v1.w;
    s = warp_sum(s);
    float mu = s * (1.f / 256.f), d, sq = 0.f;
    d = v0.x - mu; sq += d * d; d = v0.y - mu; sq += d * d;
    d = v0.z - mu; sq += d * d; d = v0.w - mu; sq += d * d;
    d = v1.x - mu; sq += d * d; d = v1.y - mu; sq += d * d;
    d = v1.z - mu; sq += d * d; d = v1.w - mu; sq += d * d;
    sq = warp_sum(sq);
    float rs = rsqrtf(sq * (1.f / 256.f) + LN_EPS);
    float4 w0 = *(const float4*)&w[lane * 4], w1 = *(const float4*)&w[128 + lane * 4];
    float4 b0 = *(const float4*)&b[lane * 4], b1 = *(const float4*)&b[128 + lane * 4];
    float4 o0, o1;
    o0.x = (v0.x - mu) * rs * w0.x + b0.x; o0.y = (v0.y - mu) * rs * w0.y + b0.y;
    o0.z = (v0.z - mu) * rs * w0.z + b0.z; o0.w = (v0.w - mu) * rs * w0.w + b0.w;
    o1.x = (v1.x - mu) * rs * w1.x + b1.x; o1.y = (v1.y - mu) * rs * w1.y + b1.y;
    o1.z = (v1.z - mu) * rs * w1.z + b1.z; o1.w = (v1.w - mu) * rs * w1.w + b1.w;
    float* orow = g_xn + (size_t)row * 256;
    *(float4*)&orow[lane * 4] = o0; *(float4*)&orow[128 + lane * 4] = o1;
}

// =============================================================================
// gemm256 (round-9/11 proven): 64x256 tile, thread tile 8x8, DOUBLE-BUFFERED.
// EPI: 0 bias, 1 gelu, 2 LN, 3 res+LN.  WTRANS: W is [256n][K]; else [K][256n].
// =============================================================================
template<int EPI, bool WTRANS>
__global__ __launch_bounds__(256, 2) void gemm256(
    const float* __restrict__ A, int lda, int strideA,
    const float* __restrict__ W, int ldw, int strideW, int kin,
    const float* __restrict__ bias, int strideB,
    float* __restrict__ C, int ldc, int strideC,
    const float* __restrict__ lnw, const float* __restrict__ lnb,
    const float* __restrict__ res, int ldres)
{
    __shared__ __align__(16) float As[2][16][68];
    __shared__ __align__(16) float Ws[2][16][260];
    const int tid = threadIdx.x, lane = tid & 31, wrp = tid >> 5;
    const int row0 = blockIdx.x * 64;
    A += (size_t)blockIdx.y * strideA;
    W += (size_t)blockIdx.y * strideW;
    C += (size_t)blockIdx.y * strideC;
    bias += (size_t)blockIdx.y * strideB;

    unsigned long long acc[8][4];
#pragma unroll
    for (int r = 0; r < 8; r++) { acc[r][0] = 0; acc[r][1] = 0; acc[r][2] = 0; acc[r][3] = 0; }

    const int am = tid >> 2, akq = (tid & 3) * 4;
    const int kr = tid >> 4, nq = (tid & 15) * 16;
    float4 av, wv[4];

    av = *(const float4*)&A[(size_t)(row0 + am) * lda + akq];
    if (WTRANS) {
#pragma unroll
        for (int oo = 0; oo < 4; oo++)
            wv[oo] = *(const float4*)&W[(size_t)(oo * 64 + am) * ldw + akq];
    } else {
#pragma unroll
        for (int q = 0; q < 4; q++)
            wv[q] = *(const float4*)&W[(size_t)kr * ldw + nq + q * 4];
    }
    { float ae[4]; *(float4*)ae = av;
#pragma unroll
      for (int j = 0; j < 4; j++) As[0][akq + j][am] = ae[j]; }
    if (WTRANS) {
#pragma unroll
        for (int oo = 0; oo < 4; oo++) { float we[4]; *(float4*)we = wv[oo];
#pragma unroll
            for (int j = 0; j < 4; j++) Ws[0][akq + j][oo * 64 + am] = we[j]; }
    } else {
#pragma unroll
        for (int q = 0; q < 4; q++) *(float4*)&Ws[0][kr][nq + q * 4] = wv[q];
    }
    __syncthreads();

    int s = 0;
    for (int kc = 0; kc < kin; kc += 16) {
        const bool more = (kc + 16) < kin;
        if (more) {
            av = *(const float4*)&A[(size_t)(row0 + am) * lda + kc + 16 + akq];
            if (WTRANS) {
#pragma unroll
                for (int oo = 0; oo < 4; oo++)
                    wv[oo] = *(const float4*)&W[(size_t)(oo * 64 + am) * ldw + kc + 16 + akq];
            } else {
#pragma unroll
                for (int q = 0; q < 4; q++)
                    wv[q] = *(const float4*)&W[(size_t)(kc + 16 + kr) * ldw + nq + q * 4];
            }
        }

#pragma unroll
        for (int k = 0; k < 16; k++) {
            ulonglong2 w0 = *(const ulonglong2*)&Ws[s][k][lane * 4];
            ulonglong2 w1 = *(const ulonglong2*)&Ws[s][k][128 + lane * 4];
            float4 aA = *(const float4*)&As[s][k][wrp * 8];
            float4 aB = *(const float4*)&As[s][k][wrp * 8 + 4];
            float ar[8] = {aA.x, aA.y, aA.z, aA.w, aB.x, aB.y, aB.z, aB.w};
#pragma unroll
            for (int r = 0; r < 8; r++) {
                unsigned long long a2 = dup2(ar[r]);
                FMA2(acc[r][0], a2, w0.x); FMA2(acc[r][1], a2, w0.y);
                FMA2(acc[r][2], a2, w1.x); FMA2(acc[r][3], a2, w1.y);
            }
        }

        if (more) {
            const int ns = s ^ 1;
            { float ae[4]; *(float4*)ae = av;
#pragma unroll
              for (int j = 0; j < 4; j++) As[ns][akq + j][am] = ae[j]; }
            if (WTRANS) {
#pragma unroll
                for (int oo = 0; oo < 4; oo++) { float we[4]; *(float4*)we = wv[oo];
#pragma unroll
                    for (int j = 0; j < 4; j++) Ws[ns][akq + j][oo * 64 + am] = we[j]; }
            } else {
#pragma unroll
                for (int q = 0; q < 4; q++) *(float4*)&Ws[ns][kr][nq + q * 4] = wv[q];
            }
            __syncthreads();
        }
        s ^= 1;
    }

    const int cA = lane * 4, cB = 128 + lane * 4;
    float4 bA = *(const float4*)&bias[cA];
    float4 bB = *(const float4*)&bias[cB];
    float4 lwA, lwB, lbA, lbB;
    if (EPI >= 2) {
        lwA = *(const float4*)&lnw[cA]; lwB = *(const float4*)&lnw[cB];
        lbA = *(const float4*)&lnb[cA]; lbB = *(const float4*)&lnb[cB];
    }
#pragma unroll
    for (int r = 0; r < 8; r++) {
        const int row = row0 + wrp * 8 + r;
        float2 p0 = u2f(acc[r][0]), p1 = u2f(acc[r][1]);
        float2 p2 = u2f(acc[r][2]), p3 = u2f(acc[r][3]);
        float v[8];
        v[0] = p0.x + bA.x; v[1] = p0.y + bA.y; v[2] = p1.x + bA.z; v[3] = p1.y + bA.w;
        v[4] = p2.x + bB.x; v[5] = p2.y + bB.y; v[6] = p3.x + bB.z; v[7] = p3.y + bB.w;
        if (EPI == 1) {
#pragma unroll
            for (int i = 0; i < 8; i++)
                v[i] = 0.5f * v[i] * (1.0f + erff(v[i] * 0.70710678118654752f));
        }
        if (EPI == 3) {
            const float* rr = res + (size_t)row * ldres;
            float4 r0 = *(const float4*)&rr[cA], r1 = *(const float4*)&rr[cB];
            v[0] += r0.x; v[1] += r0.y; v[2] += r0.z; v[3] += r0.w;
            v[4] += r1.x; v[5] += r1.y; v[6] += r1.z; v[7] += r1.w;
        }
        if (EPI >= 2) {
            float sm = v[0]+v[1]+v[2]+v[3]+v[4]+v[5]+v[6]+v[7];
            sm = warp_sum(sm);
            float mu = sm * (1.f / 256.f), sq = 0.f;
#pragma unroll
            for (int i = 0; i < 8; i++) { float d = v[i] - mu; sq += d * d; }
            sq = warp_sum(sq);
            float rs = rsqrtf(sq * (1.f / 256.f) + LN_EPS);
            v[0] = (v[0]-mu)*rs*lwA.x+lbA.x; v[1] = (v[1]-mu)*rs*lwA.y+lbA.y;
            v[2] = (v[2]-mu)*rs*lwA.z+lbA.z; v[3] = (v[3]-mu)*rs*lwA.w+lbA.w;
            v[4] = (v[4]-mu)*rs*lwB.x+lbB.x; v[5] = (v[5]-mu)*rs*lwB.y+lbB.y;
            v[6] = (v[6]-mu)*rs*lwB.z+lbB.z; v[7] = (v[7]-mu)*rs*lwB.w+lbB.w;
        }
        float4 o0 = {v[0], v[1], v[2], v[3]}, o1 = {v[4], v[5], v[6], v[7]};
        float* crow = C + (size_t)row * ldc;
        *(float4*)&crow[cA] = o0; *(float4*)&crow[cB] = o1;
    }
}

// =============================================================================
// gemm128 (round-9 proven): 64x128 tile (N-split via blockIdx.z), thread tile
// 8x4, DOUBLE-BUFFERED. EPI: 0 bias, 1 gelu.
// =============================================================================
template<int EPI>
__global__ __launch_bounds__(256, 3) void gemm128(
    const float* __restrict__ A, int lda,
    const float* __restrict__ W, int ldw, int strideW, int kin,
    const float* __restrict__ bias, int strideB,
    float* __restrict__ C, int ldc, int strideC)
{
    __shared__ __align__(16) float As[2][16][68];
    __shared__ __align__(16) float Ws[2][16][132];
    const int tid = threadIdx.x, lane = tid & 31, wrp = tid >> 5;
    const int row0 = blockIdx.x * 64;
    const int colOff = blockIdx.z * 128;
    W += (size_t)blockIdx.y * strideW + (size_t)colOff * ldw;
    C += (size_t)blockIdx.y * strideC + colOff;
    bias += (size_t)blockIdx.y * strideB + colOff;

    unsigned long long acc[8][2];
#pragma unroll
    for (int r = 0; r < 8; r++) { acc[r][0] = 0; acc[r][1] = 0; }

    const int am = tid >> 2, akq = (tid & 3) * 4;
    float4 av, wv[2];

    av = *(const float4*)&A[(size_t)(row0 + am) * lda + akq];
#pragma unroll
    for (int oo = 0; oo < 2; oo++)
        wv[oo] = *(const float4*)&W[(size_t)(oo * 64 + am) * ldw + akq];
    { float ae[4]; *(float4*)ae = av;
#pragma unroll
      for (int j = 0; j < 4; j++) As[0][akq + j][am] = ae[j]; }
#pragma unroll
    for (int oo = 0; oo < 2; oo++) {
        float we[4]; *(float4*)we = wv[oo];
#pragma unroll
        for (int j = 0; j < 4; j++) Ws[0][akq + j][oo * 64 + am] = we[j];
    }
    __syncthreads();

    int s = 0;
    for (int kc = 0; kc < kin; kc += 16) {
        const bool more = (kc + 16) < kin;
        if (more) {
            av = *(const float4*)&A[(size_t)(row0 + am) * lda + kc + 16 + akq];
#pragma unroll
            for (int oo = 0; oo < 2; oo++)
                wv[oo] = *(const float4*)&W[(size_t)(oo * 64 + am) * ldw + kc + 16 + akq];
        }

#pragma unroll
        for (int k = 0; k < 16; k++) {
            ulonglong2 w0 = *(const ulonglong2*)&Ws[s][k][lane * 4];
            float4 aA = *(const float4*)&As[s][k][wrp * 8];
            float4 aB = *(const float4*)&As[s][k][wrp * 8 + 4];
            float ar[8] = {aA.x, aA.y, aA.z, aA.w, aB.x, aB.y, aB.z, aB.w};
#pragma unroll
            for (int r = 0; r < 8; r++) {
                unsigned long long a2 = dup2(ar[r]);
                FMA2(acc[r][0], a2, w0.x); FMA2(acc[r][1], a2, w0.y);
            }
        }

        if (more) {
            const int ns = s ^ 1;
            { float ae[4]; *(float4*)ae = av;
#pragma unroll
              for (int j = 0; j < 4; j++) As[ns][akq + j][am] = ae[j]; }
#pragma unroll
            for (int oo = 0; oo < 2; oo++) {
                float we[4]; *(float4*)we = wv[oo];
#pragma unroll
                for (int j = 0; j < 4; j++) Ws[ns][akq + j][oo * 64 + am] = we[j];
            }
            __syncthreads();
        }
        s ^= 1;
    }

    const int cA = lane * 4;
    float4 bA = *(const float4*)&bias[cA];
#pragma unroll
    for (int r = 0; r < 8; r++) {
        const int row = row0 + wrp * 8 + r;
        float2 p0 = u2f(acc[r][0]), p1 = u2f(acc[r][1]);
        float v[4] = {p0.x + bA.x, p0.y + bA.y, p1.x + bA.z, p1.y + bA.w};
        if (EPI == 1) {
#pragma unroll
            for (int i = 0; i < 4; i++)
                v[i] = 0.5f * v[i] * (1.0f + erff(v[i] * 0.70710678118654752f));
        }
        float4 o0 = {v[0], v[1], v[2], v[3]};
        *(float4*)&C[(size_t)row * ldc + cA] = o0;
    }
}

// =============================================================================
// kB (round-11 core): register LN(y); VECTORIZED qWk staging (float4);
// logits 4 rows/thread c-quarter split; softmax; ybar attnT 4-head fan-out.
// =============================================================================
__global__ __launch_bounds__(256) void kB(
    const float* __restrict__ y,
    const float* __restrict__ lnk_w,
    const float* __restrict__ lnv_w, const float* __restrict__ lnv_b)
{
    __shared__ __align__(16) float ysn[32][260];
    __shared__ __align__(16) float qWk[8][260];
    __shared__ float part[4][8][33];
    __shared__ __align__(16) float attnT[32][8];
    const int tid = threadIdx.x, lane = tid & 31, w = tid >> 5;
    const int bm = blockIdx.x;
    const float* ybase = y + (size_t)bm * 8192;

    // ---- LN rows in registers (warp w -> rows 4w..4w+3) ----
#pragma unroll
    for (int r = 0; r < 4; r++) {
        const int n = w * 4 + r;
        const float* yr = ybase + n * 256;
        float4 v0 = *(const float4*)&yr[lane * 4];
        float4 v1 = *(const float4*)&yr[128 + lane * 4];
        float s = v0.x+v0.y+v0.z+v0.w + v1.x+v1.y+v1.z+v1.w;
        s = warp_sum(s);
        float mu = s * (1.f / 256.f), d, sq = 0.f;
        d=v0.x-mu; sq+=d*d; d=v0.y-mu; sq+=d*d; d=v0.z-mu; sq+=d*d; d=v0.w-mu; sq+=d*d;
        d=v1.x-mu; sq+=d*d; d=v1.y-mu; sq+=d*d; d=v1.z-mu; sq+=d*d; d=v1.w-mu; sq+=d*d;
        sq = warp_sum(sq);
        float rs = rsqrtf(sq * (1.f / 256.f) + LN_EPS);
        float4 o0 = {(v0.x-mu)*rs, (v0.y-mu)*rs, (v0.z-mu)*rs, (v0.w-mu)*rs};
        float4 o1 = {(v1.x-mu)*rs, (v1.y-mu)*rs, (v1.z-mu)*rs, (v1.w-mu)*rs};
        *(float4*)&ysn[n][lane * 4] = o0;
        *(float4*)&ysn[n][128 + lane * 4] = o1;
    }
    // ---- qWk = qWH * lnk_w (vectorized: 2 float4 per thread) ----
#pragma unroll
    for (int j = 0; j < 2; j++) {
        const int fi = j * 256 + tid;          // float4 slot 0..511
        const int h = fi >> 6, c4 = (fi & 63) * 4;
        float4 qv = *(const float4*)&g_qWH[((size_t)h * 8192 + bm) * 256 + c4];
        float4 lw = *(const float4*)&lnk_w[c4];
        float4 o = {qv.x * lw.x, qv.y * lw.y, qv.z * lw.z, qv.w * lw.w};
        *(float4*)&qWk[h][c4] = o;
    }
    __syncthreads();

    // ---- logits: thread -> (cq = tid>>6, h = tid&7, nq = (tid>>3)&7) ----
    {
        const int cq = tid >> 6, h = tid & 7, nq = (tid >> 3) & 7;
        const int c0 = cq * 64;
        unsigned long long acc0 = 0, acc1 = 0, acc2 = 0, acc3 = 0;
#pragma unroll
        for (int c4 = 0; c4 < 16; c4++) {
            ulonglong2 qk = *(const ulonglong2*)&qWk[h][c0 + c4 * 4];
            ulonglong2 a0 = *(const ulonglong2*)&ysn[nq      ][c0 + c4 * 4];
            ulonglong2 a1 = *(const ulonglong2*)&ysn[nq +  8 ][c0 + c4 * 4];
            ulonglong2 a2 = *(const ulonglong2*)&ysn[nq + 16 ][c0 + c4 * 4];
            ulonglong2 a3 = *(const ulonglong2*)&ysn[nq + 24 ][c0 + c4 * 4];
            FMA2(acc0, a0.x, qk.x); FMA2(acc0, a0.y, qk.y);
            FMA2(acc1, a1.x, qk.x); FMA2(acc1, a1.y, qk.y);
            FMA2(acc2, a2.x, qk.x); FMA2(acc2, a2.y, qk.y);
            FMA2(acc3, a3.x, qk.x); FMA2(acc3, a3.y, qk.y);
        }
        float2 p0 = u2f(acc0), p1 = u2f(acc1), p2 = u2f(acc2), p3 = u2f(acc3);
        part[cq][h][nq]      = p0.x + p0.y;
        part[cq][h][nq + 8]  = p1.x + p1.y;
        part[cq][h][nq + 16] = p2.x + p2.y;
        part[cq][h][nq + 24] = p3.x + p3.y;
    }
    __syncthreads();

    // ---- softmax per head (warp = head): combine 4 c-quarter partials ----
    {
        float v = (part[0][w][lane] + part[1][w][lane]
                 + part[2][w][lane] + part[3][w][lane]) * ATT_SCALE;
        float mx = v;
#pragma unroll
        for (int o = 16; o; o >>= 1) mx = fmaxf(mx, __shfl_xor_sync(0xffffffffu, mx, o));
        float e = __expf(v - mx);
        float s = warp_sum(e);
        attnT[lane][w] = e / s;
    }
    __syncthreads();

    // ---- ybar: thread -> (col pair cp, 4 heads) ----
    {
        int cp = tid & 127, hbase = (tid >> 7) * 4;
        float lvw0 = lnv_w[cp * 2], lvw1 = lnv_w[cp * 2 + 1];
        float lvb0 = lnv_b[cp * 2], lvb1 = lnv_b[cp * 2 + 1];
        unsigned long long acc[4] = {0, 0, 0, 0};
#pragma unroll
        for (int n = 0; n < 32; n++) {
            unsigned long long y2 = *(const unsigned long long*)&ysn[n][cp * 2];
            float4 at = *(const float4*)&attnT[n][hbase];
            FMA2(acc[0], dup2(at.x), y2);
            FMA2(acc[1], dup2(at.y), y2);
            FMA2(acc[2], dup2(at.z), y2);
            FMA2(acc[3], dup2(at.w), y2);
        }
#pragma unroll
        for (int hh = 0; hh < 4; hh++) {
            float2 p = u2f(acc[hh]);
            float2 o = {p.x * lvw0 + lvb0, p.y * lvw1 + lvb1};
            *(float2*)&g_ybarH[((size_t)(hbase + hh) * 8192 + bm) * 256 + cp * 2] = o;
        }
    }
}

// =============================================================================
// aK (round-14, measured equal-best): per head a = ybarH[h] @ Wv_h^T + bv,
// double-buffered AsT.
// =============================================================================
__global__ __launch_bounds__(256, 2) void aK(
    const float* __restrict__ Wv, const float* __restrict__ bv)
{
    __shared__ __align__(16) float WsT[256][33];
    __shared__ __align__(16) float AsT[2][16][68];
    const int tid = threadIdx.x, lane = tid & 31, wrp = tid >> 5;
    const int row0 = blockIdx.x * 64;
    const int h = blockIdx.y;
    const float* A = g_ybarH + (size_t)h * 8192 * 256;

    {
        int d = tid >> 3, c8 = (tid & 7) * 4;
#pragma unroll
        for (int j = 0; j < 8; j++) {
            int c = c8 + j * 32;
            float4 v = *(const float4*)&Wv[(size_t)(h * 32 + d) * 256 + c];
            WsT[c][d] = v.x; WsT[c+1][d] = v.y; WsT[c+2][d] = v.z; WsT[c+3][d] = v.w;
        }
    }
    unsigned long long acc[4] = {0, 0, 0, 0};
    const int am = tid >> 2, akq = (tid & 3) * 4;
    float4 av = *(const float4*)&A[(size_t)(row0 + am) * 256 + akq];
    { float ae[4]; *(float4*)ae = av;
#pragma unroll
      for (int j = 0; j < 4; j++) AsT[0][akq + j][am] = ae[j]; }
    __syncthreads();

    int s = 0;
    for (int kc = 0; kc < 256; kc += 16) {
        const bool more = (kc + 16) < 256;
        if (more)
            av = *(const float4*)&A[(size_t)(row0 + am) * 256 + kc + 16 + akq];
#pragma unroll
        for (int k = 0; k < 16; k++) {
            unsigned long long wd = dup2(WsT[kc + k][lane]);
            ulonglong2 a01 = *(const ulonglong2*)&AsT[s][k][wrp * 8];
            ulonglong2 a23 = *(const ulonglong2*)&AsT[s][k][wrp * 8 + 4];
            FMA2(acc[0], a01.x, wd); FMA2(acc[1], a01.y, wd);
            FMA2(acc[2], a23.x, wd); FMA2(acc[3], a23.y, wd);
        }
        if (more) {
            const int ns = s ^ 1;
            float ae[4]; *(float4*)ae = av;
#pragma unroll
            for (int j = 0; j < 4; j++) AsT[ns][akq + j][am] = ae[j];
            __syncthreads();
        }
        s ^= 1;
    }
    float bvv = bv[h * 32 + lane];
#pragma unroll
    for (int i = 0; i < 4; i++) {
        float2 p = u2f(acc[i]);
        int row = row0 + wrp * 8 + 2 * i;
        g_a[(size_t)row * 256 + h * 32 + lane] = p.x + bvv;
        g_a[(size_t)(row + 1) * 256 + h * 32 + lane] = p.y + bvv;
    }
}

// =============================================================================
extern "C" void kernel_launch(void* const* d_in, const int* in_sizes, int n_in,
                              void* d_out, int out_size)
{
    const float* x      = (const float*)d_in[0];
    const float* y      = (const float*)d_in[1];
    const float* lnq_w  = (const float*)d_in[2];
    const float* lnq_b  = (const float*)d_in[3];
    const float* Wq     = (const float*)d_in[4];
    const float* bq     = (const float*)d_in[5];
    const float* lnk_w  = (const float*)d_in[6];
    const float* Wk     = (const float*)d_in[8];
    const float* lnv_w  = (const float*)d_in[10];
    const float* lnv_b  = (const float*)d_in[11];
    const float* Wv     = (const float*)d_in[12];
    const float* bv     = (const float*)d_in[13];
    const float* Wp     = (const float*)d_in[14];
    const float* bp     = (const float*)d_in[15];
    const float* pre_w  = (const float*)d_in[16];
    const float* pre_b  = (const float*)d_in[17];
    const float* W1     = (const float*)d_in[18];
    const float* b1     = (const float*)d_in[19];
    const float* W2     = (const float*)d_in[20];
    const float* b2     = (const float*)d_in[21];
    const float* post_w = (const float*)d_in[22];
    const float* post_b = (const float*)d_in[23];
    float* out = (float*)d_out;

    float* zg = nullptr; cudaGetSymbolAddress((void**)&zg, g_zero);
    float* xn = nullptr; cudaGetSymbolAddress((void**)&xn, g_xn);
    float* q  = nullptr; cudaGetSymbolAddress((void**)&q,  g_q);
    float* qWH= nullptr; cudaGetSymbolAddress((void**)&qWH,g_qWH);
    float* a  = nullptr; cudaGetSymbolAddress((void**)&a,  g_a);
    float* t  = nullptr; cudaGetSymbolAddress((void**)&t,  g_t);
    float* h1 = nullptr; cudaGetSymbolAddress((void**)&h1, g_h1);

    kLNx<<<1024, 256>>>(x, lnq_w, lnq_b);
    // q = LN(x) @ Wq^T + bq   (N-split, fills all SMs)
    gemm128<0><<<dim3(128, 1, 2), 256>>>(xn, 256, Wq, 256, 0, 256, bq, 0,
                                         q, 256, 0);
    // qWH[h] = q[:, h*32:+32] @ Wk[h*32:+32, :]
    gemm256<0, false><<<dim3(128, 8), 256>>>(q, 256, 32, Wk, 256, 32 * 256, 32, zg, 0,
                                             qWH, 256, 8192 * 256, nullptr, nullptr, nullptr, 0);
    kB<<<8192, 256>>>(y, lnk_w, lnv_w, lnv_b);
    aK<<<dim3(128, 8), 256>>>(Wv, bv);
    // t = LN(a @ Wp^T + bp)   (64-row fused-LN — best known form for Wp)
    gemm256<2, true ><<<dim3(128, 1), 256>>>(a, 256, 0, Wp, 256, 0, 256, bp, 0,
                                             t, 256, 0, pre_w, pre_b, nullptr, 0);
    // h1 = gelu(t @ W1^T + b1)   (N-split, fills all SMs)
    gemm128<1><<<dim3(128, 2, 2), 256>>>(t, 256, W1, 256, 256 * 256, 256, b1, 256,
                                         h1, 512, 256);
    // out = LN(t + h1 @ W2^T + b2)   (64-row fused-LN — best known form for W2)
    gemm256<3, true ><<<dim3(128, 1), 256>>>(h1, 512, 0, W2, 512, 0, 512, b2, 0,
                                             out, 256, 0, post_w, post_b, t, 256);
}